// round 4
// baseline (speedup 1.0000x reference)
#include <cuda_runtime.h>
#include <math.h>

#define N_NODES 100000
#define N_EDGES 3200000
#define IN_CH   602
#define HID     16
#define OUT_CH  41

#define M_TILE  256
#define K_CHUNK 32

// Scratch (device globals; no allocation allowed)
__device__ float g_h1  [N_NODES * HID];
__device__ float g_agg1[N_NODES * HID];
__device__ float g_r   [N_NODES * HID];
__device__ float g_agg2[N_NODES * HID];
__device__ float g_cnt [N_NODES];

// ---------------------------------------------------------------------------
// K1: h1[N,16] = x[N,602] @ W1[602,16].
// 256-row tile; thread = 4 consecutive rows x 4 cols; float4 LDS both operands.
// ---------------------------------------------------------------------------
__global__ __launch_bounds__(256)
void gemm1_kernel(const float* __restrict__ x,
                  const float* __restrict__ W1,
                  float* __restrict__ h1) {
    __shared__ float xs[K_CHUNK][M_TILE + 4];  // pad 4: keeps float4 alignment
    __shared__ float ws[K_CHUNK][HID];

    const int tid      = threadIdx.x;
    const int row_base = blockIdx.x * M_TILE;
    const int rg = tid >> 2;        // 0..63  -> rows rg*4 .. rg*4+3
    const int cg = (tid & 3) * 4;   // 0,4,8,12 -> 4 cols

    float acc[4][4];
    #pragma unroll
    for (int i = 0; i < 4; i++)
        #pragma unroll
        for (int j = 0; j < 4; j++) acc[i][j] = 0.f;

    for (int kc = 0; kc < IN_CH; kc += K_CHUNK) {
        // stage x tile: warp reads 32 consecutive k of one row (coalesced 128B)
        #pragma unroll
        for (int i = 0; i < 32; i++) {
            int g = i * 256 + tid;
            int r = g >> 5;
            int k = g & 31;
            int gk = kc + k;
            float v = 0.f;
            if (gk < IN_CH) {
                int grow = row_base + r;
                int cr = (grow < N_NODES) ? grow : 0;   // clamp; never stored
                v = __ldg(x + (size_t)cr * IN_CH + gk);
            }
            xs[k][r] = v;
        }
        // stage W chunk: 32 x 16
        #pragma unroll
        for (int i = 0; i < 2; i++) {
            int g = i * 256 + tid;
            int k = g >> 4;
            int c = g & 15;
            int gk = kc + k;
            ws[k][c] = (gk < IN_CH) ? W1[(size_t)gk * HID + c] : 0.f;
        }
        __syncthreads();

        #pragma unroll
        for (int k = 0; k < K_CHUNK; k++) {
            float4 xv = *(const float4*)&xs[k][rg * 4];
            float4 wv = *(const float4*)&ws[k][cg];
            acc[0][0] += xv.x * wv.x; acc[0][1] += xv.x * wv.y;
            acc[0][2] += xv.x * wv.z; acc[0][3] += xv.x * wv.w;
            acc[1][0] += xv.y * wv.x; acc[1][1] += xv.y * wv.y;
            acc[1][2] += xv.y * wv.z; acc[1][3] += xv.y * wv.w;
            acc[2][0] += xv.z * wv.x; acc[2][1] += xv.z * wv.y;
            acc[2][2] += xv.z * wv.z; acc[2][3] += xv.z * wv.w;
            acc[3][0] += xv.w * wv.x; acc[3][1] += xv.w * wv.y;
            acc[3][2] += xv.w * wv.z; acc[3][3] += xv.w * wv.w;
        }
        __syncthreads();
    }

    #pragma unroll
    for (int i = 0; i < 4; i++) {
        int row = row_base + rg * 4 + i;
        if (row < N_NODES) {
            float4 v = make_float4(acc[i][0], acc[i][1], acc[i][2], acc[i][3]);
            *(float4*)(h1 + (size_t)row * 16 + cg) = v;
        }
    }
}

// ---------------------------------------------------------------------------
// K2/K4: edge scatter.  agg[dst] += h[src] (16 floats via 4x red.v4.f32).
// Optionally also counts degree into cnt (pass nullptr to skip).
// ---------------------------------------------------------------------------
__global__ void scatter_kernel(const float* __restrict__ h,
                               const int*  __restrict__ src,
                               const int*  __restrict__ dst,
                               float* __restrict__ agg,
                               float* __restrict__ cnt) {
    int e = blockIdx.x * blockDim.x + threadIdx.x;
    if (e >= N_EDGES) return;
    int s = src[e];
    int d = dst[e];
    const float4* hv = (const float4*)(h + (size_t)s * 16);
    float4 v0 = __ldg(hv + 0);
    float4 v1 = __ldg(hv + 1);
    float4 v2 = __ldg(hv + 2);
    float4 v3 = __ldg(hv + 3);
    float* ap = agg + (size_t)d * 16;
    asm volatile("red.global.add.v4.f32 [%0], {%1,%2,%3,%4};"
                 :: "l"(ap +  0), "f"(v0.x), "f"(v0.y), "f"(v0.z), "f"(v0.w) : "memory");
    asm volatile("red.global.add.v4.f32 [%0], {%1,%2,%3,%4};"
                 :: "l"(ap +  4), "f"(v1.x), "f"(v1.y), "f"(v1.z), "f"(v1.w) : "memory");
    asm volatile("red.global.add.v4.f32 [%0], {%1,%2,%3,%4};"
                 :: "l"(ap +  8), "f"(v2.x), "f"(v2.y), "f"(v2.z), "f"(v2.w) : "memory");
    asm volatile("red.global.add.v4.f32 [%0], {%1,%2,%3,%4};"
                 :: "l"(ap + 12), "f"(v3.x), "f"(v3.y), "f"(v3.z), "f"(v3.w) : "memory");
    if (cnt != nullptr) {
        asm volatile("red.global.add.f32 [%0], %1;"
                     :: "l"(cnt + d), "f"(1.0f) : "memory");
    }
}

// ---------------------------------------------------------------------------
// K3: r = relu(agg1 / max(cnt,1) + b1).  4 threads per node (float4 each).
// ---------------------------------------------------------------------------
__global__ void relu_mean_kernel(const float* __restrict__ b1,
                                 const float* __restrict__ agg1,
                                 const float* __restrict__ cnt,
                                 float* __restrict__ r) {
    int idx = blockIdx.x * blockDim.x + threadIdx.x;
    if (idx >= N_NODES * 4) return;
    int node = idx >> 2;
    int q    = idx & 3;
    float c   = fmaxf(cnt[node], 1.0f);
    float inv = 1.0f / c;
    float4 v  = ((const float4*)agg1)[idx];
    float4 bb = __ldg(((const float4*)b1) + q);
    v.x = fmaxf(v.x * inv + bb.x, 0.0f);
    v.y = fmaxf(v.y * inv + bb.y, 0.0f);
    v.z = fmaxf(v.z * inv + bb.z, 0.0f);
    v.w = fmaxf(v.w * inv + bb.w, 0.0f);
    ((float4*)r)[idx] = v;
}

// ---------------------------------------------------------------------------
// K5: out = log_softmax( (agg2/max(cnt,1)) @ W2 + b2 ).  Thread per node.
// ---------------------------------------------------------------------------
__global__ void out_kernel(const float* __restrict__ W2,
                           const float* __restrict__ b2,
                           const float* __restrict__ agg2,
                           const float* __restrict__ cnt,
                           float* __restrict__ out) {
    __shared__ float w2s[HID * OUT_CH];
    __shared__ float b2s[OUT_CH];
    for (int i = threadIdx.x; i < HID * OUT_CH; i += blockDim.x) w2s[i] = W2[i];
    for (int i = threadIdx.x; i < OUT_CH;       i += blockDim.x) b2s[i] = b2[i];
    __syncthreads();

    int n = blockIdx.x * blockDim.x + threadIdx.x;
    if (n >= N_NODES) return;

    float c   = fmaxf(cnt[n], 1.0f);
    float inv = 1.0f / c;

    const float4* av = (const float4*)(agg2 + (size_t)n * 16);
    float4 m0 = av[0], m1 = av[1], m2 = av[2], m3 = av[3];
    float m[16] = { m0.x*inv, m0.y*inv, m0.z*inv, m0.w*inv,
                    m1.x*inv, m1.y*inv, m1.z*inv, m1.w*inv,
                    m2.x*inv, m2.y*inv, m2.z*inv, m2.w*inv,
                    m3.x*inv, m3.y*inv, m3.z*inv, m3.w*inv };

    float o[OUT_CH];
    #pragma unroll
    for (int j = 0; j < OUT_CH; j++) {
        float s = b2s[j];
        #pragma unroll
        for (int k = 0; k < HID; k++)
            s += m[k] * w2s[k * OUT_CH + j];
        o[j] = s;
    }

    float mx = o[0];
    #pragma unroll
    for (int j = 1; j < OUT_CH; j++) mx = fmaxf(mx, o[j]);
    float sum = 0.0f;
    #pragma unroll
    for (int j = 0; j < OUT_CH; j++) sum += __expf(o[j] - mx);
    float ls = __logf(sum) + mx;

    float* op = out + (size_t)n * OUT_CH;
    #pragma unroll
    for (int j = 0; j < OUT_CH; j++) op[j] = o[j] - ls;
}

// ---------------------------------------------------------------------------
extern "C" void kernel_launch(void* const* d_in, const int* in_sizes, int n_in,
                              void* d_out, int out_size) {
    const float* x  = (const float*)d_in[0];
    const int*   ei = (const int*)  d_in[1];
    const float* W1 = (const float*)d_in[2];
    const float* b1 = (const float*)d_in[3];
    const float* W2 = (const float*)d_in[4];
    const float* b2 = (const float*)d_in[5];
    float* out = (float*)d_out;

    const int* src = ei;
    const int* dst = ei + N_EDGES;

    float *p_h1, *p_agg1, *p_r, *p_agg2, *p_cnt;
    cudaGetSymbolAddress((void**)&p_h1,   g_h1);
    cudaGetSymbolAddress((void**)&p_agg1, g_agg1);
    cudaGetSymbolAddress((void**)&p_r,    g_r);
    cudaGetSymbolAddress((void**)&p_agg2, g_agg2);
    cudaGetSymbolAddress((void**)&p_cnt,  g_cnt);

    cudaMemsetAsync(p_agg1, 0, sizeof(float) * N_NODES * HID);
    cudaMemsetAsync(p_agg2, 0, sizeof(float) * N_NODES * HID);
    cudaMemsetAsync(p_cnt,  0, sizeof(float) * N_NODES);

    // K1: h1 = x @ W1  (tiled SGEMM, 4x4 register blocking)
    gemm1_kernel<<<(N_NODES + M_TILE - 1) / M_TILE, 256>>>(x, W1, p_h1);

    // K2: agg1[dst] += h1[src]; cnt[dst] += 1
    scatter_kernel<<<(N_EDGES + 255) / 256, 256>>>(p_h1, src, dst, p_agg1, p_cnt);

    // K3: r = relu(agg1/max(cnt,1) + b1)
    relu_mean_kernel<<<(N_NODES * 4 + 255) / 256, 256>>>(b1, p_agg1, p_cnt, p_r);

    // K4: agg2[dst] += r[src]   (width-16 scatter; W2 applied after, by linearity)
    scatter_kernel<<<(N_EDGES + 255) / 256, 256>>>(p_r, src, dst, p_agg2, nullptr);

    // K5: out = log_softmax(agg2/max(cnt,1) @ W2 + b2)
    out_kernel<<<(N_NODES + 255) / 256, 256>>>(W2, b2, p_agg2, p_cnt, out);
}

// round 5
// speedup vs baseline: 1.6142x; 1.6142x over previous
#include <cuda_runtime.h>
#include <math.h>

#define N_NODES 100000
#define N_EDGES 3200000
#define IN_CH   602
#define HID     16
#define OUT_CH  41

#define M_TILE   256
#define K_CHUNK  32
#define SCAN_BLK 1024
#define NB_SCAN  ((N_NODES + SCAN_BLK - 1) / SCAN_BLK)   // 98

// Scratch (device globals; no allocation allowed)
__device__ float g_h1   [N_NODES * HID];
__device__ float g_r    [N_NODES * HID];
__device__ float g_mean2[N_NODES * HID];
__device__ int   g_deg  [N_NODES];
__device__ int   g_excl [N_NODES];
__device__ int   g_blksum[128];
__device__ int   g_rowptr[N_NODES + 1];
__device__ int   g_cursor[N_NODES];
__device__ int   g_csr  [N_EDGES];

// ---------------------------------------------------------------------------
// K1: h1[N,16] = x[N,602] @ W1[602,16].  (round-2 proven version: 169us)
// Tile = 256 rows x 16 cols; thread = 8 strided rows x 2 cols; scalar LDS
// stride-1 across lanes (conflict-free), W broadcast.
// ---------------------------------------------------------------------------
__global__ __launch_bounds__(256)
void gemm1_kernel(const float* __restrict__ x,
                  const float* __restrict__ W1,
                  float* __restrict__ h1) {
    __shared__ float xs[K_CHUNK][M_TILE + 1];
    __shared__ float ws[K_CHUNK][HID];

    const int tid      = threadIdx.x;
    const int row_base = blockIdx.x * M_TILE;
    const int tr = tid & 31;         // row lane (rows tr + 32*i)
    const int tc = (tid >> 5) * 2;   // column pair

    float acc[8][2];
    #pragma unroll
    for (int i = 0; i < 8; i++) { acc[i][0] = 0.f; acc[i][1] = 0.f; }

    for (int kc = 0; kc < IN_CH; kc += K_CHUNK) {
        #pragma unroll
        for (int i = 0; i < 32; i++) {
            int g = i * 256 + tid;
            int r = g >> 5;
            int k = g & 31;
            int gk = kc + k;
            float v = 0.f;
            if (gk < IN_CH) {
                int grow = row_base + r;
                int cr = (grow < N_NODES) ? grow : 0;   // clamp; never stored
                v = __ldg(x + (size_t)cr * IN_CH + gk);
            }
            xs[k][r] = v;
        }
        #pragma unroll
        for (int i = 0; i < 2; i++) {
            int g = i * 256 + tid;
            int k = g >> 4;
            int c = g & 15;
            int gk = kc + k;
            ws[k][c] = (gk < IN_CH) ? W1[(size_t)gk * HID + c] : 0.f;
        }
        __syncthreads();

        #pragma unroll
        for (int k = 0; k < K_CHUNK; k++) {
            float w0 = ws[k][tc];
            float w1 = ws[k][tc + 1];
            #pragma unroll
            for (int i = 0; i < 8; i++) {
                float xv = xs[k][tr + 32 * i];
                acc[i][0] += xv * w0;
                acc[i][1] += xv * w1;
            }
        }
        __syncthreads();
    }

    #pragma unroll
    for (int i = 0; i < 8; i++) {
        int row = row_base + tr + 32 * i;
        if (row < N_NODES) {
            float2 v = make_float2(acc[i][0], acc[i][1]);
            *(float2*)(h1 + (size_t)row * 16 + tc) = v;
        }
    }
}

// ---------------------------------------------------------------------------
// CSR construction  (round-3 proven path)
// ---------------------------------------------------------------------------
__global__ void deg_kernel(const int* __restrict__ dst, int* __restrict__ deg) {
    int e = blockIdx.x * blockDim.x + threadIdx.x;
    if (e < N_EDGES) atomicAdd(&deg[dst[e]], 1);
}

__global__ __launch_bounds__(SCAN_BLK)
void scan1_kernel(const int* __restrict__ deg,
                  int* __restrict__ excl,
                  int* __restrict__ blksum) {
    __shared__ int wsum[32];
    int tid = threadIdx.x, lane = tid & 31, wid = tid >> 5;
    int i = blockIdx.x * SCAN_BLK + tid;
    int v = (i < N_NODES) ? deg[i] : 0;
    int x = v;
    #pragma unroll
    for (int d = 1; d < 32; d <<= 1) {
        int t = __shfl_up_sync(0xffffffffu, x, d);
        if (lane >= d) x += t;
    }
    if (lane == 31) wsum[wid] = x;
    __syncthreads();
    if (wid == 0) {
        int s = wsum[lane];
        #pragma unroll
        for (int d = 1; d < 32; d <<= 1) {
            int t = __shfl_up_sync(0xffffffffu, s, d);
            if (lane >= d) s += t;
        }
        wsum[lane] = s;
    }
    __syncthreads();
    int woff = (wid == 0) ? 0 : wsum[wid - 1];
    if (i < N_NODES) excl[i] = woff + x - v;
    if (tid == SCAN_BLK - 1) blksum[blockIdx.x] = wsum[31];
}

__global__ __launch_bounds__(128)
void scan2_kernel(int* __restrict__ blksum) {
    __shared__ int ws[4];
    int tid = threadIdx.x, lane = tid & 31, wid = tid >> 5;
    int v = (tid < NB_SCAN) ? blksum[tid] : 0;
    int x = v;
    #pragma unroll
    for (int d = 1; d < 32; d <<= 1) {
        int t = __shfl_up_sync(0xffffffffu, x, d);
        if (lane >= d) x += t;
    }
    if (lane == 31) ws[wid] = x;
    __syncthreads();
    int woff = 0;
    #pragma unroll
    for (int w = 0; w < 4; w++) if (w < wid) woff += ws[w];
    if (tid < NB_SCAN) blksum[tid] = woff + x - v;
}

__global__ void scan3_kernel(const int* __restrict__ excl,
                             const int* __restrict__ blksum,
                             int* __restrict__ rowptr,
                             int* __restrict__ cursor) {
    int i = blockIdx.x * blockDim.x + threadIdx.x;
    if (i >= N_NODES) return;
    int v = excl[i] + blksum[i / SCAN_BLK];
    rowptr[i] = v;
    cursor[i] = v;
    if (i == 0) rowptr[N_NODES] = N_EDGES;
}

__global__ void fill_kernel(const int* __restrict__ src,
                            const int* __restrict__ dst,
                            int* __restrict__ cursor,
                            int* __restrict__ csr_src) {
    int e = blockIdx.x * blockDim.x + threadIdx.x;
    if (e >= N_EDGES) return;
    int slot = atomicAdd(&cursor[dst[e]], 1);
    csr_src[slot] = src[e];
}

// ---------------------------------------------------------------------------
// Gather layer: 16 threads per node (lane = channel).  out = mean of in-nbrs.
// ---------------------------------------------------------------------------
template <bool RELU>
__global__ void gather_kernel(const float* __restrict__ h,
                              const int* __restrict__ rowptr,
                              const int* __restrict__ csr_src,
                              const float* __restrict__ bias,
                              float* __restrict__ out) {
    int t = blockIdx.x * blockDim.x + threadIdx.x;
    int nid = t >> 4;
    int c   = t & 15;
    if (nid >= N_NODES) return;
    int beg = rowptr[nid];
    int end = rowptr[nid + 1];
    float s = 0.f;
    int j = beg;
    for (; j + 4 <= end; j += 4) {
        int s0 = csr_src[j], s1 = csr_src[j + 1],
            s2 = csr_src[j + 2], s3 = csr_src[j + 3];
        float v0 = h[(size_t)s0 * 16 + c];
        float v1 = h[(size_t)s1 * 16 + c];
        float v2 = h[(size_t)s2 * 16 + c];
        float v3 = h[(size_t)s3 * 16 + c];
        s += v0 + v1 + v2 + v3;
    }
    for (; j < end; j++) s += h[(size_t)csr_src[j] * 16 + c];
    float inv = 1.f / fmaxf((float)(end - beg), 1.f);
    float m = s * inv;
    if (RELU) m = fmaxf(m + bias[c], 0.f);
    out[(size_t)nid * 16 + c] = m;
}

// ---------------------------------------------------------------------------
// K5: out = log_softmax( mean2 @ W2 + b2 ).  Thread per node.
// ---------------------------------------------------------------------------
__global__ void out_kernel(const float* __restrict__ W2,
                           const float* __restrict__ b2,
                           const float* __restrict__ mean2,
                           float* __restrict__ out) {
    __shared__ float w2s[HID * OUT_CH];
    __shared__ float b2s[OUT_CH];
    for (int i = threadIdx.x; i < HID * OUT_CH; i += blockDim.x) w2s[i] = W2[i];
    for (int i = threadIdx.x; i < OUT_CH;       i += blockDim.x) b2s[i] = b2[i];
    __syncthreads();

    int n = blockIdx.x * blockDim.x + threadIdx.x;
    if (n >= N_NODES) return;

    const float4* av = (const float4*)(mean2 + (size_t)n * 16);
    float4 m0 = av[0], m1 = av[1], m2 = av[2], m3 = av[3];
    float m[16] = { m0.x, m0.y, m0.z, m0.w, m1.x, m1.y, m1.z, m1.w,
                    m2.x, m2.y, m2.z, m2.w, m3.x, m3.y, m3.z, m3.w };

    float o[OUT_CH];
    #pragma unroll
    for (int j = 0; j < OUT_CH; j++) {
        float s = b2s[j];
        #pragma unroll
        for (int k = 0; k < HID; k++)
            s += m[k] * w2s[k * OUT_CH + j];
        o[j] = s;
    }

    float mx = o[0];
    #pragma unroll
    for (int j = 1; j < OUT_CH; j++) mx = fmaxf(mx, o[j]);
    float sum = 0.0f;
    #pragma unroll
    for (int j = 0; j < OUT_CH; j++) sum += __expf(o[j] - mx);
    float ls = __logf(sum) + mx;

    float* op = out + (size_t)n * OUT_CH;
    #pragma unroll
    for (int j = 0; j < OUT_CH; j++) op[j] = o[j] - ls;
}

// ---------------------------------------------------------------------------
extern "C" void kernel_launch(void* const* d_in, const int* in_sizes, int n_in,
                              void* d_out, int out_size) {
    const float* x  = (const float*)d_in[0];
    const int*   ei = (const int*)  d_in[1];
    const float* W1 = (const float*)d_in[2];
    const float* b1 = (const float*)d_in[3];
    const float* W2 = (const float*)d_in[4];
    const float* b2 = (const float*)d_in[5];
    float* out = (float*)d_out;

    const int* src = ei;
    const int* dst = ei + N_EDGES;

    float *p_h1, *p_r, *p_mean2;
    int *p_deg, *p_excl, *p_blksum, *p_rowptr, *p_cursor, *p_csr;
    cudaGetSymbolAddress((void**)&p_h1,     g_h1);
    cudaGetSymbolAddress((void**)&p_r,      g_r);
    cudaGetSymbolAddress((void**)&p_mean2,  g_mean2);
    cudaGetSymbolAddress((void**)&p_deg,    g_deg);
    cudaGetSymbolAddress((void**)&p_excl,   g_excl);
    cudaGetSymbolAddress((void**)&p_blksum, g_blksum);
    cudaGetSymbolAddress((void**)&p_rowptr, g_rowptr);
    cudaGetSymbolAddress((void**)&p_cursor, g_cursor);
    cudaGetSymbolAddress((void**)&p_csr,    g_csr);

    cudaMemsetAsync(p_deg, 0, sizeof(int) * N_NODES);

    // CSR build: histogram -> exclusive scan -> slot fill
    deg_kernel <<<(N_EDGES + 255) / 256, 256>>>(dst, p_deg);
    scan1_kernel<<<NB_SCAN, SCAN_BLK>>>(p_deg, p_excl, p_blksum);
    scan2_kernel<<<1, 128>>>(p_blksum);
    scan3_kernel<<<(N_NODES + 255) / 256, 256>>>(p_excl, p_blksum, p_rowptr, p_cursor);
    fill_kernel <<<(N_EDGES + 255) / 256, 256>>>(src, dst, p_cursor, p_csr);

    // K1: h1 = x @ W1  (8x2 register blocking — proven fastest)
    gemm1_kernel<<<(N_NODES + M_TILE - 1) / M_TILE, 256>>>(x, W1, p_h1);

    // Layer 1 aggregate: r = relu(mean_nbr(h1) + b1)
    gather_kernel<true> <<<(N_NODES * 16 + 255) / 256, 256>>>(p_h1, p_rowptr, p_csr, b1, p_r);

    // Layer 2 aggregate: mean2 = mean_nbr(r)   (W2 applied after, by linearity)
    gather_kernel<false><<<(N_NODES * 16 + 255) / 256, 256>>>(p_r, p_rowptr, p_csr, b1, p_mean2);

    // K5: out = log_softmax(mean2 @ W2 + b2)
    out_kernel<<<(N_NODES + 255) / 256, 256>>>(W2, b2, p_mean2, out);
}